// round 13
// baseline (speedup 1.0000x reference)
#include <cuda_runtime.h>
#include <cstdint>

#define W 8192
#define H 2048
#define NPIX (W * H)
#define THREADS 256
#define TILE_PX 1024
#define CHUNKS (TILE_PX / THREADS)        // 4
#define NTILES (NPIX / TILE_PX)           // 16384
#define GRID 888                          // 148 SMs x 6 resident; 888*1024 = 111*8192
#define IMG_BYTES (TILE_PX * 16)          // 16384
#define OUT_BYTES (TILE_PX * 12)          // 12288

#define FOV_SPAN     0.5235987755982988f
#define FOV_ABS_DOWN 0.2617993877991494f
#define TWO_PI       6.283185307179586f
#define PI_F         3.141592653589793f

// Rotation by 256 column steps: pi/16
#define ROT_C 0.9807852804032304f
#define ROT_S 0.1950903220161283f

__device__ __forceinline__ uint32_t smem_u32(const void* p) {
    uint32_t a;
    asm("{ .reg .u64 t; cvta.to.shared.u64 t, %1; cvt.u32.u64 %0, t; }"
        : "=r"(a) : "l"(p));
    return a;
}

__device__ __forceinline__ void mbar_wait(uint32_t mb, int phase) {
    asm volatile(
        "{\n\t"
        ".reg .pred P;\n\t"
        "WAIT_%=:\n\t"
        "mbarrier.try_wait.parity.acquire.cta.shared::cta.b64 P, [%0], %1, 0x989680;\n\t"
        "@P bra DONE_%=;\n\t"
        "bra WAIT_%=;\n\t"
        "DONE_%=:\n\t"
        "}" :: "r"(mb), "r"(phase) : "memory");
}

// Persistent double-buffered TMA pipeline.
// 888 blocks grid-stride over 16384 tiles (1024 px each). While tile k is
// computed+stored from one 16KB buffer, the TMA load of the block's next tile
// streams into the other. After pipeline fill, blocks never wait on loads and
// the chip-level read/write streams are continuous (vs R9's phase-locked
// load->compute->store blocks). 888*1024 = 111 rows exactly, so each block's
// column window (and its sincosf yaw set) is LOOP-INVARIANT: one sincosf per
// thread for the whole kernel; only sinf(pitch) varies per tile.
__global__ void __launch_bounds__(THREADS)
proj_to_pointcloud_kernel(const float* __restrict__ img, float* __restrict__ out) {
    __shared__ alignas(128) float s_buf[2][TILE_PX * 4];   // 2 x 16 KB, dual-use
    __shared__ alignas(8)   uint64_t s_mbar[2];

    int t = threadIdx.x;
    uint32_t mb0 = smem_u32(&s_mbar[0]);
    uint32_t mb1 = smem_u32(&s_mbar[1]);

    if (t == 0) {
        asm volatile("mbarrier.init.shared.b64 [%0], %1;" :: "r"(mb0), "r"(1));
        asm volatile("mbarrier.init.shared.b64 [%0], %1;" :: "r"(mb1), "r"(1));
    }
    __syncthreads();

    long tile0 = blockIdx.x;
    int j0 = (int)((tile0 * TILE_PX) & (W - 1));           // invariant across the loop

    // One sincosf per thread for the whole kernel.
    float yaw = (float)(j0 + t) * (TWO_PI / (float)W) - PI_F;
    float c0, s0;
    sincosf(yaw, &s0, &c0);

    // Prime the pipeline: load first tile into buf 0.
    if (t == 0) {
        asm volatile("mbarrier.arrive.expect_tx.shared.b64 _, [%0], %1;"
                     :: "r"(mb0), "r"(IMG_BYTES) : "memory");
        asm volatile(
            "cp.async.bulk.shared::cta.global.mbarrier::complete_tx::bytes "
            "[%0], [%1], %2, [%3];"
            :: "r"(smem_u32(s_buf[0])), "l"(img + (tile0 * TILE_PX << 2)),
               "n"(IMG_BYTES), "r"(mb0) : "memory");
    }

    int ph0 = 0, ph1 = 0;
    long k = 0;
    for (long ti = tile0; ti < NTILES; ti += GRID, ++k) {
        int b = (int)(k & 1);
        uint32_t mb = b ? mb1 : mb0;

        // Wait for tile ti's data (pipeline keeps this hot after fill).
        mbar_wait(mb, b ? ph1 : ph0);
        if (b) ph1 ^= 1; else ph0 ^= 1;

        // Issue load of the NEXT tile into the other buffer.
        long tn = ti + GRID;
        if (t == 0 && tn < NTILES) {
            // The other buffer's last store must have finished reading smem.
            asm volatile("cp.async.bulk.wait_group.read 0;" ::: "memory");
            uint32_t mbn = b ? mb0 : mb1;
            asm volatile("mbarrier.arrive.expect_tx.shared.b64 _, [%0], %1;"
                         :: "r"(mbn), "r"(IMG_BYTES) : "memory");
            asm volatile(
                "cp.async.bulk.shared::cta.global.mbarrier::complete_tx::bytes "
                "[%0], [%1], %2, [%3];"
                :: "r"(smem_u32(s_buf[b ^ 1])), "l"(img + (tn * TILE_PX << 2)),
                   "n"(IMG_BYTES), "r"(mbn) : "memory");
        }

        // Per-tile pitch (row varies by 111 per step).
        int row = (int)((ti * TILE_PX) >> 13);
        float pitch = (1.0f - (float)row / (float)H) * FOV_SPAN - FOV_ABS_DOWN;
        float sp = sinf(pitch);

        // Extract depths to registers, then overwrite buffer with xyz.
        float d[CHUNKS];
        #pragma unroll
        for (int i = 0; i < CHUNKS; i++)
            d[i] = s_buf[b][4 * (i * THREADS + t) + 3];
        __syncthreads();

        float c = c0, s = s0;
        #pragma unroll
        for (int i = 0; i < CHUNKS; i++) {
            int p = i * THREADS + t;
            s_buf[b][3 * p + 0] =  d[i] * c;
            s_buf[b][3 * p + 1] = -d[i] * s;
            s_buf[b][3 * p + 2] =  d[i] * sp;
            float cn = fmaf(c, ROT_C, -s * ROT_S);
            float sn = fmaf(s, ROT_C,  c * ROT_S);
            c = cn; s = sn;
        }
        __syncthreads();

        if (t == 0) {
            asm volatile("fence.proxy.async.shared::cta;" ::: "memory");
            asm volatile(
                "cp.async.bulk.global.shared::cta.bulk_group [%0], [%1], %2;"
                :: "l"(out + ti * TILE_PX * 3), "r"(smem_u32(s_buf[b])),
                   "n"(OUT_BYTES) : "memory");
            asm volatile("cp.async.bulk.commit_group;" ::: "memory");
        }
    }

    // Keep smem alive until the final store's read completes.
    if (t == 0) {
        asm volatile("cp.async.bulk.wait_group.read 0;" ::: "memory");
    }
}

extern "C" void kernel_launch(void* const* d_in, const int* in_sizes, int n_in,
                              void* d_out, int out_size) {
    const float* img = (const float*)d_in[0];
    float* out = (float*)d_out;
    proj_to_pointcloud_kernel<<<GRID, THREADS>>>(img, out);
}

// round 14
// speedup vs baseline: 1.0837x; 1.0837x over previous
#include <cuda_runtime.h>
#include <cstdint>

#define W 8192
#define H 2048
#define NPIX (W * H)
#define THREADS 256
#define PX_PER_BLOCK 1024
#define CHUNKS (PX_PER_BLOCK / THREADS)          // 4
#define NBLOCKS (NPIX / PX_PER_BLOCK)            // 16384
#define IMG_BYTES_PER_BLOCK (PX_PER_BLOCK * 16)  // 16384
#define OUT_BYTES_PER_BLOCK (PX_PER_BLOCK * 12)  // 12288

#define FOV_SPAN     0.5235987755982988f
#define FOV_ABS_DOWN 0.2617993877991494f
#define TWO_PI       6.283185307179586f
#define PI_F         3.141592653589793f

// Rotation by 256 column steps: delta = 256 * 2*pi/8192 = pi/16
#define ROT_C 0.9807852804032304f
#define ROT_S 0.1950903220161283f

__device__ __forceinline__ uint32_t smem_u32(const void* p) {
    uint32_t a;
    asm("{ .reg .u64 t; cvta.to.shared.u64 t, %1; cvt.u32.u64 %0, t; }"
        : "=r"(a) : "l"(p));
    return a;
}

// R8 structure at 1024-px tiles WITH buffer reuse: smem drops to 16.5 KB,
// so 8 blocks/SM become resident (vs R9's 6 at 60% occ) -> 100% occupancy,
// 33% more TMA loads in flight chip-wide, finer read/write burst interleave.
// This isolates the last untested first-order variable (concurrency) against
// the 6.21 TB/s sustained-rate plateau seen across all other configs.
__global__ void __launch_bounds__(THREADS)
proj_to_pointcloud_kernel(const float* __restrict__ img, float* __restrict__ out) {
    __shared__ alignas(128) float s_buf[PX_PER_BLOCK * 4];   // 16 KB, dual-use
    __shared__ alignas(8)   uint64_t s_mbar;

    int t = threadIdx.x;
    long blockBase = (long)blockIdx.x * PX_PER_BLOCK;        // 1024 | 8192: one row
    int row = (int)(blockBase >> 13);
    int j0  = (int)(blockBase & (W - 1));
    uint32_t mb = smem_u32(&s_mbar);

    if (t == 0) {
        asm volatile("mbarrier.init.shared.b64 [%0], %1;" :: "r"(mb), "r"(1));
    }
    __syncthreads();

    if (t == 0) {
        asm volatile("mbarrier.arrive.expect_tx.shared.b64 _, [%0], %1;"
                     :: "r"(mb), "r"(IMG_BYTES_PER_BLOCK) : "memory");
        asm volatile(
            "cp.async.bulk.shared::cta.global.mbarrier::complete_tx::bytes "
            "[%0], [%1], %2, [%3];"
            :: "r"(smem_u32(s_buf)), "l"(img + (blockBase << 2)),
               "n"(IMG_BYTES_PER_BLOCK), "r"(mb) : "memory");
    }

    // ---- trig, overlapped with the TMA load ----
    float yaw = (float)(j0 + t) * (TWO_PI / (float)W) - PI_F;
    float s, c;
    sincosf(yaw, &s, &c);
    float pitch = (1.0f - (float)row / (float)H) * FOV_SPAN - FOV_ABS_DOWN;
    float sp = sinf(pitch);

    // ---- wait for image tile ----
    asm volatile(
        "{\n\t"
        ".reg .pred P;\n\t"
        "WAIT_%=:\n\t"
        "mbarrier.try_wait.parity.acquire.cta.shared::cta.b64 P, [%0], %1, 0x989680;\n\t"
        "@P bra DONE_%=;\n\t"
        "bra WAIT_%=;\n\t"
        "DONE_%=:\n\t"
        "}" :: "r"(mb), "r"(0) : "memory");

    // ---- extract depths to registers (buffer gets overwritten next) ----
    float d[CHUNKS];
    #pragma unroll
    for (int i = 0; i < CHUNKS; i++) {
        d[i] = s_buf[4 * (i * THREADS + t) + 3];
    }
    __syncthreads();   // all reads done before any xyz overwrite

    #pragma unroll
    for (int i = 0; i < CHUNKS; i++) {
        int p = i * THREADS + t;
        s_buf[3 * p + 0] =  d[i] * c;        // stride-3 scalar STS: conflict-free
        s_buf[3 * p + 1] = -d[i] * s;
        s_buf[3 * p + 2] =  d[i] * sp;
        // advance yaw by 256 columns (pi/16)
        float cn = fmaf(c, ROT_C, -s * ROT_S);
        float sn = fmaf(s, ROT_C,  c * ROT_S);
        c = cn; s = sn;
    }

    __syncthreads();

    if (t == 0) {
        asm volatile("fence.proxy.async.shared::cta;" ::: "memory");
        asm volatile(
            "cp.async.bulk.global.shared::cta.bulk_group [%0], [%1], %2;"
            :: "l"(out + blockBase * 3), "r"(smem_u32(s_buf)),
               "n"(OUT_BYTES_PER_BLOCK) : "memory");
        asm volatile("cp.async.bulk.commit_group;" ::: "memory");
        // keep smem alive until the TMA has read it
        asm volatile("cp.async.bulk.wait_group.read 0;" ::: "memory");
    }
}

extern "C" void kernel_launch(void* const* d_in, const int* in_sizes, int n_in,
                              void* d_out, int out_size) {
    const float* img = (const float*)d_in[0];
    float* out = (float*)d_out;
    proj_to_pointcloud_kernel<<<NBLOCKS, THREADS>>>(img, out);
}